// round 3
// baseline (speedup 1.0000x reference)
#include <cuda_runtime.h>
#include <math.h>

// Problem constants
#define Bb  4
#define Ss  2048
#define Dd  1024
#define Hh  16
#define HDd 64
#define Mm  (Bb*Ss)          // 8192

// Scratch (no allocation allowed -> __device__ globals)
__device__ float g_q[Bb*Hh*Ss*HDd];   // [B,H,S,HD]
__device__ float g_k[Bb*Hh*Ss*HDd];
__device__ float g_v[Bb*Hh*Ss*HDd];
__device__ float g_o[Bb*Ss*Dd];       // [B,S,D] (merged heads)

// ---------------------------------------------------------------------------
// GEMM: out = A[M,K] @ W[K,N] + bias
// MODE 0/1/2: A = x (param), out = g_q/g_k/g_v in head-split [B,H,S,HD] layout
// MODE 3:     A = g_o,       out = param (plain row-major [M,N])
// Tiling: 128x128x16, 256 threads, 8x8 per thread (split 4+4).
// ---------------------------------------------------------------------------
template<int MODE>
__global__ __launch_bounds__(256)
void sgemm_bias(const float* __restrict__ A_param,
                const float* __restrict__ W,
                const float* __restrict__ bias,
                float* __restrict__ out_param)
{
    const int K = Dd, N = Dd;
    __shared__ __align__(16) float As[16][128];
    __shared__ __align__(16) float Bs[16][128];

    const float* A = (MODE == 3) ? g_o : A_param;
    float* outp;
    if      (MODE == 0) outp = g_q;
    else if (MODE == 1) outp = g_k;
    else if (MODE == 2) outp = g_v;
    else                outp = out_param;

    const int t  = threadIdx.x;
    const int tx = t & 15;
    const int ty = t >> 4;
    const int bm = blockIdx.y * 128;
    const int bn = blockIdx.x * 128;

    float acc[8][8];
    #pragma unroll
    for (int i = 0; i < 8; i++)
        #pragma unroll
        for (int j = 0; j < 8; j++) acc[i][j] = 0.f;

    // A tile loader: thread -> rows ar and ar+64, k-colgroup = (t%4)*4
    // 256 threads * 2 float4 = 2048 elements = 128 rows x 16 k. (R1 bug: only half.)
    const int ar = t >> 2;          // 0..63
    const int ac = (t & 3) * 4;     // 0,4,8,12
    // B tile loader: rows br and br+8, col4 = t%32
    const int br = t >> 5;
    const int bc = (t & 31) * 4;

    const float* Aptr = A + (size_t)(bm + ar) * K + ac;
    const float* Wptr = W + (size_t)br * N + bn + bc;

    for (int k0 = 0; k0 < K; k0 += 16) {
        float4 av0 = *(const float4*)(Aptr + k0);
        float4 av1 = *(const float4*)(Aptr + (size_t)64 * K + k0);
        As[ac + 0][ar] = av0.x;
        As[ac + 1][ar] = av0.y;
        As[ac + 2][ar] = av0.z;
        As[ac + 3][ar] = av0.w;
        As[ac + 0][ar + 64] = av1.x;
        As[ac + 1][ar + 64] = av1.y;
        As[ac + 2][ar + 64] = av1.z;
        As[ac + 3][ar + 64] = av1.w;
        *(float4*)&Bs[br    ][bc] = *(const float4*)(Wptr + (size_t)k0 * N);
        *(float4*)&Bs[br + 8][bc] = *(const float4*)(Wptr + (size_t)(k0 + 8) * N);
        __syncthreads();

        #pragma unroll
        for (int kk = 0; kk < 16; kk++) {
            float a[8], b[8];
            *(float4*)&a[0] = *(const float4*)&As[kk][ty * 4];
            *(float4*)&a[4] = *(const float4*)&As[kk][64 + ty * 4];
            *(float4*)&b[0] = *(const float4*)&Bs[kk][tx * 4];
            *(float4*)&b[4] = *(const float4*)&Bs[kk][64 + tx * 4];
            #pragma unroll
            for (int i = 0; i < 8; i++)
                #pragma unroll
                for (int j = 0; j < 8; j++)
                    acc[i][j] += a[i] * b[j];
        }
        __syncthreads();
    }

    // Epilogue: bias + store
    #pragma unroll
    for (int i = 0; i < 8; i++) {
        const int mrow = bm + ((i < 4) ? (ty * 4 + i) : (64 + ty * 4 + i - 4));
        #pragma unroll
        for (int j = 0; j < 8; j++) {
            const int ncol = bn + ((j < 4) ? (tx * 4 + j) : (64 + tx * 4 + j - 4));
            const float v = acc[i][j] + bias[ncol];
            if (MODE <= 2) {
                // head-split: [B,H,S,HD]
                const int b = mrow / Ss, s = mrow % Ss;
                const int h = ncol / HDd, d = ncol % HDd;
                outp[(((size_t)b * Hh + h) * Ss + s) * HDd + d] = v;
            } else {
                outp[(size_t)mrow * Dd + ncol] = v;
            }
        }
    }
}

// ---------------------------------------------------------------------------
// Flash attention (causal), fp32.
// grid: (S/128, B*H); block: 128 threads; 1 thread = 1 query row.
// K/V staged in smem in 64-key tiles; online softmax in 16-key chunks to
// bound register pressure (q[64] + acc[64] + s[16] live).
// ---------------------------------------------------------------------------
__global__ __launch_bounds__(128)
void flash_attn()
{
    __shared__ float4 k_s[64][16];   // 64 keys x 64 floats
    __shared__ float4 v_s[64][16];

    const int tid = threadIdx.x;
    const int q0  = blockIdx.x * 128;
    const int bh  = blockIdx.y;          // b*H + h
    const int r   = q0 + tid;            // query row (always < S)

    // Load q row, fold in 1/sqrt(HD) = 0.125
    const float4* qsrc = (const float4*)(g_q + ((size_t)bh * Ss + r) * HDd);
    float4 qv[16];
    #pragma unroll
    for (int i = 0; i < 16; i++) {
        float4 x = qsrc[i];
        x.x *= 0.125f; x.y *= 0.125f; x.z *= 0.125f; x.w *= 0.125f;
        qv[i] = x;
    }

    float4 accv[16];
    #pragma unroll
    for (int i = 0; i < 16; i++) accv[i] = make_float4(0.f, 0.f, 0.f, 0.f);

    float m_run = -INFINITY;
    float l_run = 0.f;

    const int kb_end = q0 / 64 + 1;      // last key block needed by this q block
    const float4* kbase = (const float4*)(g_k + (size_t)bh * Ss * HDd);
    const float4* vbase = (const float4*)(g_v + (size_t)bh * Ss * HDd);

    for (int kb = 0; kb <= kb_end; kb++) {
        __syncthreads();
        // cooperative tile load: 1024 float4 each, 8 per thread, coalesced
        const float4* ksrc = kbase + (size_t)kb * 64 * 16;
        const float4* vsrc = vbase + (size_t)kb * 64 * 16;
        #pragma unroll
        for (int i = 0; i < 8; i++) {
            const int idx = tid + i * 128;
            ((float4*)k_s)[idx] = ksrc[idx];
            ((float4*)v_s)[idx] = vsrc[idx];
        }
        __syncthreads();

        #pragma unroll 1
        for (int sub = 0; sub < 4; sub++) {
            // ---- scores for 16 keys ----
            float s[16];
            float chmax = -INFINITY;
            #pragma unroll
            for (int jj = 0; jj < 16; jj++) {
                const int j = sub * 16 + jj;
                const float4* kr = k_s[j];
                float d0 = 0.f;
                #pragma unroll
                for (int dq = 0; dq < 16; dq++) {
                    const float4 kk4 = kr[dq];
                    d0 += qv[dq].x * kk4.x;
                    d0 += qv[dq].y * kk4.y;
                    d0 += qv[dq].z * kk4.z;
                    d0 += qv[dq].w * kk4.w;
                }
                const int key = kb * 64 + j;
                s[jj] = (key <= r) ? d0 : -INFINITY;
                chmax = fmaxf(chmax, s[jj]);
            }

            // ---- online softmax update ----
            const float mnew  = fmaxf(m_run, chmax);
            const float scale = __expf(m_run - mnew);   // 0 when m_run==-inf
            float psum = 0.f;
            #pragma unroll
            for (int jj = 0; jj < 16; jj++) {
                s[jj] = __expf(s[jj] - mnew);           // 0 for masked keys
                psum += s[jj];
            }
            l_run = l_run * scale + psum;
            m_run = mnew;

            #pragma unroll
            for (int dq = 0; dq < 16; dq++) {
                accv[dq].x *= scale; accv[dq].y *= scale;
                accv[dq].z *= scale; accv[dq].w *= scale;
            }

            // ---- P @ V ----
            #pragma unroll
            for (int jj = 0; jj < 16; jj++) {
                const int j = sub * 16 + jj;
                const float p = s[jj];
                const float4* vr = v_s[j];
                #pragma unroll
                for (int dq = 0; dq < 16; dq++) {
                    const float4 vv = vr[dq];
                    accv[dq].x += p * vv.x;
                    accv[dq].y += p * vv.y;
                    accv[dq].z += p * vv.z;
                    accv[dq].w += p * vv.w;
                }
            }
        }
    }

    // normalize + write merged-head layout [B,S,D]
    const float inv = 1.f / l_run;
    const int b = bh / Hh, h = bh % Hh;
    float4* orow = (float4*)(g_o + ((size_t)b * Ss + r) * Dd + h * HDd);
    #pragma unroll
    for (int dq = 0; dq < 16; dq++) {
        float4 o = accv[dq];
        o.x *= inv; o.y *= inv; o.z *= inv; o.w *= inv;
        orow[dq] = o;
    }
}

// ---------------------------------------------------------------------------
extern "C" void kernel_launch(void* const* d_in, const int* in_sizes, int n_in,
                              void* d_out, int out_size)
{
    const float* x  = (const float*)d_in[0];
    const float* wq = (const float*)d_in[1];
    const float* bq = (const float*)d_in[2];
    const float* wk = (const float*)d_in[3];
    const float* bk = (const float*)d_in[4];
    const float* wv = (const float*)d_in[5];
    const float* bv = (const float*)d_in[6];
    const float* wo = (const float*)d_in[7];
    const float* bo = (const float*)d_in[8];
    float* out = (float*)d_out;

    dim3 ggrid(Dd / 128, Mm / 128);       // (8, 64)
    sgemm_bias<0><<<ggrid, 256>>>(x, wq, bq, nullptr);
    sgemm_bias<1><<<ggrid, 256>>>(x, wk, bk, nullptr);
    sgemm_bias<2><<<ggrid, 256>>>(x, wv, bv, nullptr);

    dim3 agrid(Ss / 128, Bb * Hh);        // (16, 64)
    flash_attn<<<agrid, 128>>>();

    sgemm_bias<3><<<ggrid, 256>>>(nullptr, wo, bo, out);
}

// round 4
// speedup vs baseline: 1.3144x; 1.3144x over previous
#include <cuda_runtime.h>
#include <math.h>
#include <stdint.h>

// Problem constants
#define Bb  4
#define Ss  2048
#define Dd  1024
#define Hh  16
#define HDd 64
#define Mm  (Bb*Ss)          // 8192

// Scratch (no allocation allowed -> __device__ globals)
__device__ __align__(16) float g_q[Bb*Hh*Ss*HDd];   // [B,H,S,HD]
__device__ __align__(16) float g_k[Bb*Hh*Ss*HDd];
__device__ __align__(16) float g_v[Bb*Hh*Ss*HDd];
__device__ __align__(16) float g_o[Bb*Ss*Dd];       // [B,S,D] (merged heads)

__device__ __forceinline__ uint32_t to_tf32(float f) {
    uint32_t u;
    asm("cvt.rna.tf32.f32 %0, %1;" : "=r"(u) : "f"(f));
    return u;
}

__device__ __forceinline__ void mma_tf32(float c[4],
                                         uint32_t a0, uint32_t a1, uint32_t a2, uint32_t a3,
                                         uint32_t b0, uint32_t b1) {
    asm volatile(
        "mma.sync.aligned.m16n8k8.row.col.f32.tf32.tf32.f32 "
        "{%0,%1,%2,%3}, {%4,%5,%6,%7}, {%8,%9}, {%0,%1,%2,%3};"
        : "+f"(c[0]), "+f"(c[1]), "+f"(c[2]), "+f"(c[3])
        : "r"(a0), "r"(a1), "r"(a2), "r"(a3), "r"(b0), "r"(b1));
}

// ---------------------------------------------------------------------------
// tf32 tensor-core GEMM: out = A[M,1024] @ W[1024,1024] + bias
// MODE 0/1/2: A = x, out = g_q/g_k/g_v head-split [B,H,S,HD]
// MODE 3:     A = g_o, out = d_out row-major [M,N]
// Block tile 128x128, K-tile 16. 256 threads = 8 warps, warp tile 32x64
// (warp_m = wid%4, warp_n = wid/4). mma.m16n8k8: 2 m-atoms x 8 n-atoms.
// Inputs rounded to tf32 (cvt.rna) at smem-store time; fp32 accumulate.
// ---------------------------------------------------------------------------
template<int MODE>
__global__ __launch_bounds__(256)
void tc_gemm(const float* __restrict__ A_param,
             const float* __restrict__ W,
             const float* __restrict__ bias,
             float* __restrict__ out_param)
{
    const int K = Dd, N = Dd;
    __shared__ __align__(16) uint32_t As[16][132];   // [k][m], pad 4
    __shared__ __align__(16) uint32_t Bs[16][132];   // [k][n], pad 4

    const float* A = (MODE == 3) ? g_o : A_param;
    float* outp;
    if      (MODE == 0) outp = g_q;
    else if (MODE == 1) outp = g_k;
    else if (MODE == 2) outp = g_v;
    else                outp = out_param;

    const int t    = threadIdx.x;
    const int lane = t & 31;
    const int wid  = t >> 5;
    const int wm   = (wid & 3) * 32;    // warp m-offset in tile
    const int wn   = (wid >> 2) * 64;   // warp n-offset in tile
    const int g    = lane >> 2;         // groupID 0..7
    const int tig  = lane & 3;          // threadID_in_group 0..3

    const int bm = blockIdx.y * 128;
    const int bn = blockIdx.x * 128;

    float acc[2][8][4];
    #pragma unroll
    for (int ma = 0; ma < 2; ma++)
        #pragma unroll
        for (int na = 0; na < 8; na++)
            #pragma unroll
            for (int i = 0; i < 4; i++) acc[ma][na][i] = 0.f;

    // A loader: rows ar, ar+64; k-cols ac..ac+3 (covers 128m x 16k)
    const int ar = t >> 2;
    const int ac = (t & 3) * 4;
    // B loader: k-rows br, br+8; n-cols bc..bc+3 (covers 16k x 128n)
    const int br = t >> 5;
    const int bc = (t & 31) * 4;

    const float* Aptr = A + (size_t)(bm + ar) * K + ac;
    const float* Wptr = W + (size_t)br * N + bn + bc;

    for (int k0 = 0; k0 < K; k0 += 16) {
        float4 av0 = *(const float4*)(Aptr + k0);
        float4 av1 = *(const float4*)(Aptr + (size_t)64 * K + k0);
        As[ac + 0][ar] = to_tf32(av0.x);
        As[ac + 1][ar] = to_tf32(av0.y);
        As[ac + 2][ar] = to_tf32(av0.z);
        As[ac + 3][ar] = to_tf32(av0.w);
        As[ac + 0][ar + 64] = to_tf32(av1.x);
        As[ac + 1][ar + 64] = to_tf32(av1.y);
        As[ac + 2][ar + 64] = to_tf32(av1.z);
        As[ac + 3][ar + 64] = to_tf32(av1.w);
        float4 bv0 = *(const float4*)(Wptr + (size_t)k0 * N);
        float4 bv1 = *(const float4*)(Wptr + (size_t)(k0 + 8) * N);
        Bs[br][bc + 0] = to_tf32(bv0.x);
        Bs[br][bc + 1] = to_tf32(bv0.y);
        Bs[br][bc + 2] = to_tf32(bv0.z);
        Bs[br][bc + 3] = to_tf32(bv0.w);
        Bs[br + 8][bc + 0] = to_tf32(bv1.x);
        Bs[br + 8][bc + 1] = to_tf32(bv1.y);
        Bs[br + 8][bc + 2] = to_tf32(bv1.z);
        Bs[br + 8][bc + 3] = to_tf32(bv1.w);
        __syncthreads();

        #pragma unroll
        for (int ks = 0; ks < 16; ks += 8) {
            uint32_t a[2][4];
            #pragma unroll
            for (int ma = 0; ma < 2; ma++) {
                const int m0 = wm + ma * 16 + g;
                a[ma][0] = As[ks + tig    ][m0];
                a[ma][1] = As[ks + tig    ][m0 + 8];
                a[ma][2] = As[ks + tig + 4][m0];
                a[ma][3] = As[ks + tig + 4][m0 + 8];
            }
            #pragma unroll
            for (int na = 0; na < 8; na++) {
                const int n0 = wn + na * 8 + g;
                uint32_t b0 = Bs[ks + tig    ][n0];
                uint32_t b1 = Bs[ks + tig + 4][n0];
                #pragma unroll
                for (int ma = 0; ma < 2; ma++)
                    mma_tf32(acc[ma][na], a[ma][0], a[ma][1], a[ma][2], a[ma][3], b0, b1);
            }
        }
        __syncthreads();
    }

    // Epilogue: bias + store.
    // c0:(row=g, col=tig*2) c1:(g, tig*2+1) c2:(g+8, tig*2) c3:(g+8, tig*2+1)
    #pragma unroll
    for (int ma = 0; ma < 2; ma++) {
        #pragma unroll
        for (int na = 0; na < 8; na++) {
            const int row0 = bm + wm + ma * 16 + g;
            const int col  = bn + wn + na * 8 + tig * 2;
            const float bia0 = bias[col], bia1 = bias[col + 1];
            #pragma unroll
            for (int half = 0; half < 2; half++) {
                const int mrow = row0 + half * 8;
                float2 v;
                v.x = acc[ma][na][half * 2 + 0] + bia0;
                v.y = acc[ma][na][half * 2 + 1] + bia1;
                if (MODE <= 2) {
                    const int b = mrow / Ss, s = mrow % Ss;
                    const int h = col / HDd, d = col % HDd;
                    *(float2*)&outp[(((size_t)b * Hh + h) * Ss + s) * HDd + d] = v;
                } else {
                    *(float2*)&outp[(size_t)mrow * Dd + col] = v;
                }
            }
        }
    }
}

// ---------------------------------------------------------------------------
// Flash attention (causal), fp32 SIMT (unchanged from R3).
// grid: (S/128, B*H); block: 128 threads; 1 thread = 1 query row.
// ---------------------------------------------------------------------------
__global__ __launch_bounds__(128)
void flash_attn()
{
    __shared__ float4 k_s[64][16];   // 64 keys x 64 floats
    __shared__ float4 v_s[64][16];

    const int tid = threadIdx.x;
    const int q0  = blockIdx.x * 128;
    const int bh  = blockIdx.y;          // b*H + h
    const int r   = q0 + tid;            // query row

    const float4* qsrc = (const float4*)(g_q + ((size_t)bh * Ss + r) * HDd);
    float4 qv[16];
    #pragma unroll
    for (int i = 0; i < 16; i++) {
        float4 x = qsrc[i];
        x.x *= 0.125f; x.y *= 0.125f; x.z *= 0.125f; x.w *= 0.125f;
        qv[i] = x;
    }

    float4 accv[16];
    #pragma unroll
    for (int i = 0; i < 16; i++) accv[i] = make_float4(0.f, 0.f, 0.f, 0.f);

    float m_run = -INFINITY;
    float l_run = 0.f;

    const int kb_end = q0 / 64 + 1;
    const float4* kbase = (const float4*)(g_k + (size_t)bh * Ss * HDd);
    const float4* vbase = (const float4*)(g_v + (size_t)bh * Ss * HDd);

    for (int kb = 0; kb <= kb_end; kb++) {
        __syncthreads();
        const float4* ksrc = kbase + (size_t)kb * 64 * 16;
        const float4* vsrc = vbase + (size_t)kb * 64 * 16;
        #pragma unroll
        for (int i = 0; i < 8; i++) {
            const int idx = tid + i * 128;
            ((float4*)k_s)[idx] = ksrc[idx];
            ((float4*)v_s)[idx] = vsrc[idx];
        }
        __syncthreads();

        #pragma unroll 1
        for (int sub = 0; sub < 4; sub++) {
            float s[16];
            float chmax = -INFINITY;
            #pragma unroll
            for (int jj = 0; jj < 16; jj++) {
                const int j = sub * 16 + jj;
                const float4* kr = k_s[j];
                float d0 = 0.f;
                #pragma unroll
                for (int dq = 0; dq < 16; dq++) {
                    const float4 kk4 = kr[dq];
                    d0 += qv[dq].x * kk4.x;
                    d0 += qv[dq].y * kk4.y;
                    d0 += qv[dq].z * kk4.z;
                    d0 += qv[dq].w * kk4.w;
                }
                const int key = kb * 64 + j;
                s[jj] = (key <= r) ? d0 : -INFINITY;
                chmax = fmaxf(chmax, s[jj]);
            }

            const float mnew  = fmaxf(m_run, chmax);
            const float scale = __expf(m_run - mnew);
            float psum = 0.f;
            #pragma unroll
            for (int jj = 0; jj < 16; jj++) {
                s[jj] = __expf(s[jj] - mnew);
                psum += s[jj];
            }
            l_run = l_run * scale + psum;
            m_run = mnew;

            #pragma unroll
            for (int dq = 0; dq < 16; dq++) {
                accv[dq].x *= scale; accv[dq].y *= scale;
                accv[dq].z *= scale; accv[dq].w *= scale;
            }

            #pragma unroll
            for (int jj = 0; jj < 16; jj++) {
                const int j = sub * 16 + jj;
                const float p = s[jj];
                const float4* vr = v_s[j];
                #pragma unroll
                for (int dq = 0; dq < 16; dq++) {
                    const float4 vv = vr[dq];
                    accv[dq].x += p * vv.x;
                    accv[dq].y += p * vv.y;
                    accv[dq].z += p * vv.z;
                    accv[dq].w += p * vv.w;
                }
            }
        }
    }

    const float inv = 1.f / l_run;
    const int b = bh / Hh, h = bh % Hh;
    float4* orow = (float4*)(g_o + ((size_t)b * Ss + r) * Dd + h * HDd);
    #pragma unroll
    for (int dq = 0; dq < 16; dq++) {
        float4 o = accv[dq];
        o.x *= inv; o.y *= inv; o.z *= inv; o.w *= inv;
        orow[dq] = o;
    }
}

// ---------------------------------------------------------------------------
extern "C" void kernel_launch(void* const* d_in, const int* in_sizes, int n_in,
                              void* d_out, int out_size)
{
    const float* x  = (const float*)d_in[0];
    const float* wq = (const float*)d_in[1];
    const float* bq = (const float*)d_in[2];
    const float* wk = (const float*)d_in[3];
    const float* bk = (const float*)d_in[4];
    const float* wv = (const float*)d_in[5];
    const float* bv = (const float*)d_in[6];
    const float* wo = (const float*)d_in[7];
    const float* bo = (const float*)d_in[8];
    float* out = (float*)d_out;

    dim3 ggrid(Dd / 128, Mm / 128);       // (8, 64)
    tc_gemm<0><<<ggrid, 256>>>(x, wq, bq, nullptr);
    tc_gemm<1><<<ggrid, 256>>>(x, wk, bk, nullptr);
    tc_gemm<2><<<ggrid, 256>>>(x, wv, bv, nullptr);

    dim3 agrid(Ss / 128, Bb * Hh);        // (16, 64)
    flash_attn<<<agrid, 128>>>();

    tc_gemm<3><<<ggrid, 256>>>(nullptr, wo, bo, out);
}

// round 5
// speedup vs baseline: 2.4819x; 1.8883x over previous
#include <cuda_runtime.h>
#include <math.h>
#include <stdint.h>

// Problem constants
#define Bb  4
#define Ss  2048
#define Dd  1024
#define Hh  16
#define HDd 64
#define Mm  (Bb*Ss)          // 8192

// Scratch (no allocation allowed -> __device__ globals)
__device__ __align__(16) float g_q[Bb*Hh*Ss*HDd];   // [B,H,S,HD]
__device__ __align__(16) float g_k[Bb*Hh*Ss*HDd];
__device__ __align__(16) float g_v[Bb*Hh*Ss*HDd];
__device__ __align__(16) float g_o[Bb*Ss*Dd];       // [B,S,D] (merged heads)

__device__ __forceinline__ uint32_t to_tf32(float f) {
    uint32_t u;
    asm("cvt.rna.tf32.f32 %0, %1;" : "=r"(u) : "f"(f));
    return u;
}

__device__ __forceinline__ void mma_tf32(float c[4],
                                         uint32_t a0, uint32_t a1, uint32_t a2, uint32_t a3,
                                         uint32_t b0, uint32_t b1) {
    asm volatile(
        "mma.sync.aligned.m16n8k8.row.col.f32.tf32.tf32.f32 "
        "{%0,%1,%2,%3}, {%4,%5,%6,%7}, {%8,%9}, {%0,%1,%2,%3};"
        : "+f"(c[0]), "+f"(c[1]), "+f"(c[2]), "+f"(c[3])
        : "r"(a0), "r"(a1), "r"(a2), "r"(a3), "r"(b0), "r"(b1));
}

// ---------------------------------------------------------------------------
// tf32 tensor-core GEMM (unchanged from R4): out = A[M,1024] @ W[1024,1024]+b
// ---------------------------------------------------------------------------
template<int MODE>
__global__ __launch_bounds__(256)
void tc_gemm(const float* __restrict__ A_param,
             const float* __restrict__ W,
             const float* __restrict__ bias,
             float* __restrict__ out_param)
{
    const int K = Dd, N = Dd;
    __shared__ __align__(16) uint32_t As[16][132];
    __shared__ __align__(16) uint32_t Bs[16][132];

    const float* A = (MODE == 3) ? g_o : A_param;
    float* outp;
    if      (MODE == 0) outp = g_q;
    else if (MODE == 1) outp = g_k;
    else if (MODE == 2) outp = g_v;
    else                outp = out_param;

    const int t    = threadIdx.x;
    const int lane = t & 31;
    const int wid  = t >> 5;
    const int wm   = (wid & 3) * 32;
    const int wn   = (wid >> 2) * 64;
    const int g    = lane >> 2;
    const int tig  = lane & 3;

    const int bm = blockIdx.y * 128;
    const int bn = blockIdx.x * 128;

    float acc[2][8][4];
    #pragma unroll
    for (int ma = 0; ma < 2; ma++)
        #pragma unroll
        for (int na = 0; na < 8; na++)
            #pragma unroll
            for (int i = 0; i < 4; i++) acc[ma][na][i] = 0.f;

    const int ar = t >> 2;
    const int ac = (t & 3) * 4;
    const int br = t >> 5;
    const int bc = (t & 31) * 4;

    const float* Aptr = A + (size_t)(bm + ar) * K + ac;
    const float* Wptr = W + (size_t)br * N + bn + bc;

    for (int k0 = 0; k0 < K; k0 += 16) {
        float4 av0 = *(const float4*)(Aptr + k0);
        float4 av1 = *(const float4*)(Aptr + (size_t)64 * K + k0);
        As[ac + 0][ar] = to_tf32(av0.x);
        As[ac + 1][ar] = to_tf32(av0.y);
        As[ac + 2][ar] = to_tf32(av0.z);
        As[ac + 3][ar] = to_tf32(av0.w);
        As[ac + 0][ar + 64] = to_tf32(av1.x);
        As[ac + 1][ar + 64] = to_tf32(av1.y);
        As[ac + 2][ar + 64] = to_tf32(av1.z);
        As[ac + 3][ar + 64] = to_tf32(av1.w);
        float4 bv0 = *(const float4*)(Wptr + (size_t)k0 * N);
        float4 bv1 = *(const float4*)(Wptr + (size_t)(k0 + 8) * N);
        Bs[br][bc + 0] = to_tf32(bv0.x);
        Bs[br][bc + 1] = to_tf32(bv0.y);
        Bs[br][bc + 2] = to_tf32(bv0.z);
        Bs[br][bc + 3] = to_tf32(bv0.w);
        Bs[br + 8][bc + 0] = to_tf32(bv1.x);
        Bs[br + 8][bc + 1] = to_tf32(bv1.y);
        Bs[br + 8][bc + 2] = to_tf32(bv1.z);
        Bs[br + 8][bc + 3] = to_tf32(bv1.w);
        __syncthreads();

        #pragma unroll
        for (int ks = 0; ks < 16; ks += 8) {
            uint32_t a[2][4];
            #pragma unroll
            for (int ma = 0; ma < 2; ma++) {
                const int m0 = wm + ma * 16 + g;
                a[ma][0] = As[ks + tig    ][m0];
                a[ma][1] = As[ks + tig    ][m0 + 8];
                a[ma][2] = As[ks + tig + 4][m0];
                a[ma][3] = As[ks + tig + 4][m0 + 8];
            }
            #pragma unroll
            for (int na = 0; na < 8; na++) {
                const int n0 = wn + na * 8 + g;
                uint32_t b0 = Bs[ks + tig    ][n0];
                uint32_t b1 = Bs[ks + tig + 4][n0];
                #pragma unroll
                for (int ma = 0; ma < 2; ma++)
                    mma_tf32(acc[ma][na], a[ma][0], a[ma][1], a[ma][2], a[ma][3], b0, b1);
            }
        }
        __syncthreads();
    }

    #pragma unroll
    for (int ma = 0; ma < 2; ma++) {
        #pragma unroll
        for (int na = 0; na < 8; na++) {
            const int row0 = bm + wm + ma * 16 + g;
            const int col  = bn + wn + na * 8 + tig * 2;
            const float bia0 = bias[col], bia1 = bias[col + 1];
            #pragma unroll
            for (int half = 0; half < 2; half++) {
                const int mrow = row0 + half * 8;
                float2 v;
                v.x = acc[ma][na][half * 2 + 0] + bia0;
                v.y = acc[ma][na][half * 2 + 1] + bia1;
                if (MODE <= 2) {
                    const int b = mrow / Ss, s = mrow % Ss;
                    const int h = col / HDd, d = col % HDd;
                    *(float2*)&outp[(((size_t)b * Hh + h) * Ss + s) * HDd + d] = v;
                } else {
                    *(float2*)&outp[(size_t)mrow * Dd + col] = v;
                }
            }
        }
    }
}

// ---------------------------------------------------------------------------
// Tensor-core flash attention (causal), tf32 mma, FA2-style.
// Block: 4 warps, 64 q-rows (16/warp). Key tile 64. Online softmax.
// smem pitches chosen conflict-free for the mma fragment patterns:
//   K pitch 68 words (bank = 4g+tig+8c), V pitch 72 (bank = 8tig+g+8na),
//   P pitch 68 (loads 4g+tig).
// ---------------------------------------------------------------------------
#define KP 68
#define VP 72
#define PP 68
#define FA_SMEM ((64*KP + 64*VP + 4*16*PP) * 4)   // 53248 bytes

__global__ __launch_bounds__(128)
void flash_attn_tc()
{
    extern __shared__ uint32_t dsm[];
    uint32_t* Ks = dsm;                    // [64][KP]
    uint32_t* Vs = dsm + 64 * KP;          // [64][VP]
    uint32_t* Ps = dsm + 64 * KP + 64 * VP;// [4][16][PP]

    const int tid  = threadIdx.x;
    const int lane = tid & 31;
    const int wid  = tid >> 5;
    const int g    = lane >> 2;
    const int tig  = lane & 3;
    const int q0   = blockIdx.x * 64;
    const int bh   = blockIdx.y;
    const int qr0  = q0 + wid * 16;

    const float* qb = g_q + (size_t)bh * Ss * HDd;
    const float* kb = g_k + (size_t)bh * Ss * HDd;
    const float* vb = g_v + (size_t)bh * Ss * HDd;

    // Q fragments (scale 1/8 folded in). a0=(g,tig) a1=(g+8,tig) a2=(g,tig+4) a3=(g+8,tig+4)
    uint32_t qf[8][4];
    #pragma unroll
    for (int c = 0; c < 8; c++) {
        qf[c][0] = to_tf32(qb[(size_t)(qr0 + g    ) * HDd + c * 8 + tig    ] * 0.125f);
        qf[c][1] = to_tf32(qb[(size_t)(qr0 + g + 8) * HDd + c * 8 + tig    ] * 0.125f);
        qf[c][2] = to_tf32(qb[(size_t)(qr0 + g    ) * HDd + c * 8 + tig + 4] * 0.125f);
        qf[c][3] = to_tf32(qb[(size_t)(qr0 + g + 8) * HDd + c * 8 + tig + 4] * 0.125f);
    }

    float acc[8][4];                       // O accumulator: na over hd
    #pragma unroll
    for (int na = 0; na < 8; na++)
        #pragma unroll
        for (int i = 0; i < 4; i++) acc[na][i] = 0.f;

    float m_lo = -INFINITY, m_hi = -INFINITY;
    float l_lo = 0.f, l_hi = 0.f;

    uint32_t* Pw = Ps + wid * 16 * PP;
    const int nt = q0 / 64 + 1;            // tiles needed (causal)

    for (int kt = 0; kt < nt; kt++) {
        __syncthreads();
        // Load K/V tile (64 keys x 64 hd), convert to tf32, store padded.
        #pragma unroll
        for (int i = 0; i < 8; i++) {
            const int idx = tid + i * 128;     // 0..1023 float4 slots
            const int row = idx >> 4;
            const int c4  = (idx & 15) * 4;
            float4 kv = *(const float4*)(kb + (size_t)(kt * 64 + row) * HDd + c4);
            float4 vv = *(const float4*)(vb + (size_t)(kt * 64 + row) * HDd + c4);
            uint4 kt4 = make_uint4(to_tf32(kv.x), to_tf32(kv.y), to_tf32(kv.z), to_tf32(kv.w));
            uint4 vt4 = make_uint4(to_tf32(vv.x), to_tf32(vv.y), to_tf32(vv.z), to_tf32(vv.w));
            *(uint4*)&Ks[row * KP + c4] = kt4;
            *(uint4*)&Vs[row * VP + c4] = vt4;
        }
        __syncthreads();

        // ---- S = Q K^T (rows g,g+8; cols na*8 + 2tig, +1) ----
        float s[8][4];
        #pragma unroll
        for (int na = 0; na < 8; na++)
            #pragma unroll
            for (int i = 0; i < 4; i++) s[na][i] = 0.f;

        #pragma unroll
        for (int c = 0; c < 8; c++) {
            #pragma unroll
            for (int na = 0; na < 8; na++) {
                uint32_t b0 = Ks[(na * 8 + g) * KP + c * 8 + tig    ];
                uint32_t b1 = Ks[(na * 8 + g) * KP + c * 8 + tig + 4];
                mma_tf32(s[na], qf[c][0], qf[c][1], qf[c][2], qf[c][3], b0, b1);
            }
        }

        // ---- causal mask (diagonal tile only) ----
        if (kt == nt - 1) {
            const int rlo = qr0 + g, rhi = qr0 + g + 8;
            #pragma unroll
            for (int na = 0; na < 8; na++) {
                const int c0 = kt * 64 + na * 8 + tig * 2;
                const int c1 = c0 + 1;
                if (c0 > rlo) s[na][0] = -INFINITY;
                if (c1 > rlo) s[na][1] = -INFINITY;
                if (c0 > rhi) s[na][2] = -INFINITY;
                if (c1 > rhi) s[na][3] = -INFINITY;
            }
        }

        // ---- online softmax ----
        float tm_lo = -INFINITY, tm_hi = -INFINITY;
        #pragma unroll
        for (int na = 0; na < 8; na++) {
            tm_lo = fmaxf(tm_lo, fmaxf(s[na][0], s[na][1]));
            tm_hi = fmaxf(tm_hi, fmaxf(s[na][2], s[na][3]));
        }
        tm_lo = fmaxf(tm_lo, __shfl_xor_sync(0xffffffffu, tm_lo, 1));
        tm_lo = fmaxf(tm_lo, __shfl_xor_sync(0xffffffffu, tm_lo, 2));
        tm_hi = fmaxf(tm_hi, __shfl_xor_sync(0xffffffffu, tm_hi, 1));
        tm_hi = fmaxf(tm_hi, __shfl_xor_sync(0xffffffffu, tm_hi, 2));

        const float mn_lo = fmaxf(m_lo, tm_lo);
        const float mn_hi = fmaxf(m_hi, tm_hi);
        const float sc_lo = __expf(m_lo - mn_lo);
        const float sc_hi = __expf(m_hi - mn_hi);

        float sum_lo = 0.f, sum_hi = 0.f;
        #pragma unroll
        for (int na = 0; na < 8; na++) {
            s[na][0] = __expf(s[na][0] - mn_lo);
            s[na][1] = __expf(s[na][1] - mn_lo);
            s[na][2] = __expf(s[na][2] - mn_hi);
            s[na][3] = __expf(s[na][3] - mn_hi);
            sum_lo += s[na][0] + s[na][1];
            sum_hi += s[na][2] + s[na][3];
        }
        sum_lo += __shfl_xor_sync(0xffffffffu, sum_lo, 1);
        sum_lo += __shfl_xor_sync(0xffffffffu, sum_lo, 2);
        sum_hi += __shfl_xor_sync(0xffffffffu, sum_hi, 1);
        sum_hi += __shfl_xor_sync(0xffffffffu, sum_hi, 2);

        l_lo = l_lo * sc_lo + sum_lo;  m_lo = mn_lo;
        l_hi = l_hi * sc_hi + sum_hi;  m_hi = mn_hi;

        #pragma unroll
        for (int na = 0; na < 8; na++) {
            acc[na][0] *= sc_lo; acc[na][1] *= sc_lo;
            acc[na][2] *= sc_hi; acc[na][3] *= sc_hi;
        }

        // ---- stage P (tf32) to per-warp smem, re-read as A fragments ----
        #pragma unroll
        for (int na = 0; na < 8; na++) {
            uint2 plo = make_uint2(to_tf32(s[na][0]), to_tf32(s[na][1]));
            uint2 phi = make_uint2(to_tf32(s[na][2]), to_tf32(s[na][3]));
            *(uint2*)&Pw[(g    ) * PP + na * 8 + tig * 2] = plo;
            *(uint2*)&Pw[(g + 8) * PP + na * 8 + tig * 2] = phi;
        }
        __syncwarp();

        // ---- O += P V ----
        #pragma unroll
        for (int c = 0; c < 8; c++) {
            uint32_t a0 = Pw[(g    ) * PP + c * 8 + tig    ];
            uint32_t a1 = Pw[(g + 8) * PP + c * 8 + tig    ];
            uint32_t a2 = Pw[(g    ) * PP + c * 8 + tig + 4];
            uint32_t a3 = Pw[(g + 8) * PP + c * 8 + tig + 4];
            #pragma unroll
            for (int na = 0; na < 8; na++) {
                uint32_t b0 = Vs[(c * 8 + tig    ) * VP + na * 8 + g];
                uint32_t b1 = Vs[(c * 8 + tig + 4) * VP + na * 8 + g];
                mma_tf32(acc[na], a0, a1, a2, a3, b0, b1);
            }
        }
    }

    // ---- epilogue: normalize, write merged-head [B,S,D] ----
    const float inv_lo = 1.f / l_lo;
    const float inv_hi = 1.f / l_hi;
    const int b = bh / Hh, h = bh % Hh;
    float* olo = g_o + ((size_t)b * Ss + (qr0 + g    )) * Dd + h * HDd;
    float* ohi = g_o + ((size_t)b * Ss + (qr0 + g + 8)) * Dd + h * HDd;
    #pragma unroll
    for (int na = 0; na < 8; na++) {
        float2 vlo = make_float2(acc[na][0] * inv_lo, acc[na][1] * inv_lo);
        float2 vhi = make_float2(acc[na][2] * inv_hi, acc[na][3] * inv_hi);
        *(float2*)&olo[na * 8 + tig * 2] = vlo;
        *(float2*)&ohi[na * 8 + tig * 2] = vhi;
    }
}

// ---------------------------------------------------------------------------
extern "C" void kernel_launch(void* const* d_in, const int* in_sizes, int n_in,
                              void* d_out, int out_size)
{
    const float* x  = (const float*)d_in[0];
    const float* wq = (const float*)d_in[1];
    const float* bq = (const float*)d_in[2];
    const float* wk = (const float*)d_in[3];
    const float* bk = (const float*)d_in[4];
    const float* wv = (const float*)d_in[5];
    const float* bv = (const float*)d_in[6];
    const float* wo = (const float*)d_in[7];
    const float* bo = (const float*)d_in[8];
    float* out = (float*)d_out;

    cudaFuncSetAttribute(flash_attn_tc,
                         cudaFuncAttributeMaxDynamicSharedMemorySize, FA_SMEM);

    dim3 ggrid(Dd / 128, Mm / 128);       // (8, 64)
    tc_gemm<0><<<ggrid, 256>>>(x, wq, bq, nullptr);
    tc_gemm<1><<<ggrid, 256>>>(x, wk, bk, nullptr);
    tc_gemm<2><<<ggrid, 256>>>(x, wv, bv, nullptr);

    dim3 agrid(Ss / 64, Bb * Hh);         // (32, 64)
    flash_attn_tc<<<agrid, 128, FA_SMEM>>>();

    tc_gemm<3><<<ggrid, 256>>>(nullptr, wo, bo, out);
}

// round 6
// speedup vs baseline: 3.3251x; 1.3397x over previous
#include <cuda_runtime.h>
#include <math.h>
#include <stdint.h>

// Problem constants
#define Bb  4
#define Ss  2048
#define Dd  1024
#define Hh  16
#define HDd 64
#define Mm  (Bb*Ss)          // 8192

// Scratch (no allocation allowed -> __device__ globals)
__device__ __align__(16) float g_q[Bb*Hh*Ss*HDd];   // [B,H,S,HD]
__device__ __align__(16) float g_k[Bb*Hh*Ss*HDd];
__device__ __align__(16) float g_v[Bb*Hh*Ss*HDd];
__device__ __align__(16) float g_o[Bb*Ss*Dd];       // [B,S,D] (merged heads)

__device__ __forceinline__ uint32_t to_tf32(float f) {
    uint32_t u;
    asm("cvt.rna.tf32.f32 %0, %1;" : "=r"(u) : "f"(f));
    return u;
}

__device__ __forceinline__ void mma_tf32(float c[4],
                                         uint32_t a0, uint32_t a1, uint32_t a2, uint32_t a3,
                                         uint32_t b0, uint32_t b1) {
    asm volatile(
        "mma.sync.aligned.m16n8k8.row.col.f32.tf32.tf32.f32 "
        "{%0,%1,%2,%3}, {%4,%5,%6,%7}, {%8,%9}, {%0,%1,%2,%3};"
        : "+f"(c[0]), "+f"(c[1]), "+f"(c[2]), "+f"(c[3])
        : "r"(a0), "r"(a1), "r"(a2), "r"(a3), "r"(b0), "r"(b1));
}

// ---------------------------------------------------------------------------
// tf32 tensor-core GEMM, 2-stage double-buffered pipeline.
// out = A[M,1024] @ W[1024,1024] + bias
// MODE 0/1/2: A = x, out = g_q/g_k/g_v head-split [B,H,S,HD]
// MODE 3:     A = g_o, out = d_out row-major [M,N]
// Block tile 128x128, K-tile 16, 256 threads = 8 warps (warp tile 32x64).
// Per iteration: prefetch LDG(kt+1) -> compute MMA from buf[cur] ->
// cvt+STS into buf[cur^1] -> 1 barrier.
// ---------------------------------------------------------------------------
template<int MODE>
__global__ __launch_bounds__(256, 2)
void tc_gemm(const float* __restrict__ A_param,
             const float* __restrict__ W,
             const float* __restrict__ bias,
             float* __restrict__ out_param)
{
    const int K = Dd, N = Dd;
    __shared__ __align__(16) uint32_t As[2][16][132];
    __shared__ __align__(16) uint32_t Bs[2][16][132];

    const float* A = (MODE == 3) ? g_o : A_param;
    float* outp;
    if      (MODE == 0) outp = g_q;
    else if (MODE == 1) outp = g_k;
    else if (MODE == 2) outp = g_v;
    else                outp = out_param;

    const int t    = threadIdx.x;
    const int lane = t & 31;
    const int wid  = t >> 5;
    const int wm   = (wid & 3) * 32;
    const int wn   = (wid >> 2) * 64;
    const int g    = lane >> 2;
    const int tig  = lane & 3;

    const int bm = blockIdx.y * 128;
    const int bn = blockIdx.x * 128;

    float acc[2][8][4];
    #pragma unroll
    for (int ma = 0; ma < 2; ma++)
        #pragma unroll
        for (int na = 0; na < 8; na++)
            #pragma unroll
            for (int i = 0; i < 4; i++) acc[ma][na][i] = 0.f;

    // A loader: rows ar, ar+64; k-cols ac..ac+3 (covers 128m x 16k)
    const int ar = t >> 2;
    const int ac = (t & 3) * 4;
    // B loader: k-rows br, br+8; n-cols bc..bc+3 (covers 16k x 128n)
    const int br = t >> 5;
    const int bc = (t & 31) * 4;

    const float* Aptr = A + (size_t)(bm + ar) * K + ac;
    const float* Wptr = W + (size_t)br * N + bn + bc;

    // ---- prologue: tile 0 into buf 0 ----
    float4 av0 = *(const float4*)(Aptr);
    float4 av1 = *(const float4*)(Aptr + (size_t)64 * K);
    float4 bv0 = *(const float4*)(Wptr);
    float4 bv1 = *(const float4*)(Wptr + (size_t)8 * N);

    As[0][ac + 0][ar] = to_tf32(av0.x);
    As[0][ac + 1][ar] = to_tf32(av0.y);
    As[0][ac + 2][ar] = to_tf32(av0.z);
    As[0][ac + 3][ar] = to_tf32(av0.w);
    As[0][ac + 0][ar + 64] = to_tf32(av1.x);
    As[0][ac + 1][ar + 64] = to_tf32(av1.y);
    As[0][ac + 2][ar + 64] = to_tf32(av1.z);
    As[0][ac + 3][ar + 64] = to_tf32(av1.w);
    {
        uint4 b0q = make_uint4(to_tf32(bv0.x), to_tf32(bv0.y), to_tf32(bv0.z), to_tf32(bv0.w));
        uint4 b1q = make_uint4(to_tf32(bv1.x), to_tf32(bv1.y), to_tf32(bv1.z), to_tf32(bv1.w));
        *(uint4*)&Bs[0][br][bc]     = b0q;
        *(uint4*)&Bs[0][br + 8][bc] = b1q;
    }
    __syncthreads();

    const int NT = K / 16;   // 64
    for (int kt = 0; kt < NT; kt++) {
        const int cur = kt & 1;

        // ---- prefetch next tile (global -> regs); latency hidden by MMAs ----
        if (kt + 1 < NT) {
            const int k0 = (kt + 1) * 16;
            av0 = *(const float4*)(Aptr + k0);
            av1 = *(const float4*)(Aptr + (size_t)64 * K + k0);
            bv0 = *(const float4*)(Wptr + (size_t)k0 * N);
            bv1 = *(const float4*)(Wptr + (size_t)(k0 + 8) * N);
        }

        // ---- compute from buf[cur] ----
        #pragma unroll
        for (int ks = 0; ks < 16; ks += 8) {
            uint32_t a[2][4];
            #pragma unroll
            for (int ma = 0; ma < 2; ma++) {
                const int m0 = wm + ma * 16 + g;
                a[ma][0] = As[cur][ks + tig    ][m0];
                a[ma][1] = As[cur][ks + tig    ][m0 + 8];
                a[ma][2] = As[cur][ks + tig + 4][m0];
                a[ma][3] = As[cur][ks + tig + 4][m0 + 8];
            }
            #pragma unroll
            for (int na = 0; na < 8; na++) {
                const int n0 = wn + na * 8 + g;
                uint32_t b0 = Bs[cur][ks + tig    ][n0];
                uint32_t b1 = Bs[cur][ks + tig + 4][n0];
                #pragma unroll
                for (int ma = 0; ma < 2; ma++)
                    mma_tf32(acc[ma][na], a[ma][0], a[ma][1], a[ma][2], a[ma][3], b0, b1);
            }
        }

        // ---- store prefetched tile into the other buffer ----
        if (kt + 1 < NT) {
            const int nxt = cur ^ 1;
            As[nxt][ac + 0][ar] = to_tf32(av0.x);
            As[nxt][ac + 1][ar] = to_tf32(av0.y);
            As[nxt][ac + 2][ar] = to_tf32(av0.z);
            As[nxt][ac + 3][ar] = to_tf32(av0.w);
            As[nxt][ac + 0][ar + 64] = to_tf32(av1.x);
            As[nxt][ac + 1][ar + 64] = to_tf32(av1.y);
            As[nxt][ac + 2][ar + 64] = to_tf32(av1.z);
            As[nxt][ac + 3][ar + 64] = to_tf32(av1.w);
            uint4 b0q = make_uint4(to_tf32(bv0.x), to_tf32(bv0.y), to_tf32(bv0.z), to_tf32(bv0.w));
            uint4 b1q = make_uint4(to_tf32(bv1.x), to_tf32(bv1.y), to_tf32(bv1.z), to_tf32(bv1.w));
            *(uint4*)&Bs[nxt][br][bc]     = b0q;
            *(uint4*)&Bs[nxt][br + 8][bc] = b1q;
        }
        __syncthreads();
    }

    // ---- epilogue: bias + store ----
    #pragma unroll
    for (int ma = 0; ma < 2; ma++) {
        #pragma unroll
        for (int na = 0; na < 8; na++) {
            const int row0 = bm + wm + ma * 16 + g;
            const int col  = bn + wn + na * 8 + tig * 2;
            const float bia0 = bias[col], bia1 = bias[col + 1];
            #pragma unroll
            for (int half = 0; half < 2; half++) {
                const int mrow = row0 + half * 8;
                float2 v;
                v.x = acc[ma][na][half * 2 + 0] + bia0;
                v.y = acc[ma][na][half * 2 + 1] + bia1;
                if (MODE <= 2) {
                    const int b = mrow / Ss, s = mrow % Ss;
                    const int h = col / HDd, d = col % HDd;
                    *(float2*)&outp[(((size_t)b * Hh + h) * Ss + s) * HDd + d] = v;
                } else {
                    *(float2*)&outp[(size_t)mrow * Dd + col] = v;
                }
            }
        }
    }
}

// ---------------------------------------------------------------------------
// Tensor-core flash attention (causal), tf32 mma, FA2-style (unchanged R5).
// ---------------------------------------------------------------------------
#define KP 68
#define VP 72
#define PP 68
#define FA_SMEM ((64*KP + 64*VP + 4*16*PP) * 4)   // 53248 bytes

__global__ __launch_bounds__(128)
void flash_attn_tc()
{
    extern __shared__ uint32_t dsm[];
    uint32_t* Ks = dsm;                    // [64][KP]
    uint32_t* Vs = dsm + 64 * KP;          // [64][VP]
    uint32_t* Ps = dsm + 64 * KP + 64 * VP;// [4][16][PP]

    const int tid  = threadIdx.x;
    const int lane = tid & 31;
    const int wid  = tid >> 5;
    const int g    = lane >> 2;
    const int tig  = lane & 3;
    const int q0   = blockIdx.x * 64;
    const int bh   = blockIdx.y;
    const int qr0  = q0 + wid * 16;

    const float* qb = g_q + (size_t)bh * Ss * HDd;
    const float* kb = g_k + (size_t)bh * Ss * HDd;
    const float* vb = g_v + (size_t)bh * Ss * HDd;

    uint32_t qf[8][4];
    #pragma unroll
    for (int c = 0; c < 8; c++) {
        qf[c][0] = to_tf32(qb[(size_t)(qr0 + g    ) * HDd + c * 8 + tig    ] * 0.125f);
        qf[c][1] = to_tf32(qb[(size_t)(qr0 + g + 8) * HDd + c * 8 + tig    ] * 0.125f);
        qf[c][2] = to_tf32(qb[(size_t)(qr0 + g    ) * HDd + c * 8 + tig + 4] * 0.125f);
        qf[c][3] = to_tf32(qb[(size_t)(qr0 + g + 8) * HDd + c * 8 + tig + 4] * 0.125f);
    }

    float acc[8][4];
    #pragma unroll
    for (int na = 0; na < 8; na++)
        #pragma unroll
        for (int i = 0; i < 4; i++) acc[na][i] = 0.f;

    float m_lo = -INFINITY, m_hi = -INFINITY;
    float l_lo = 0.f, l_hi = 0.f;

    uint32_t* Pw = Ps + wid * 16 * PP;
    const int nt = q0 / 64 + 1;

    for (int kt = 0; kt < nt; kt++) {
        __syncthreads();
        #pragma unroll
        for (int i = 0; i < 8; i++) {
            const int idx = tid + i * 128;
            const int row = idx >> 4;
            const int c4  = (idx & 15) * 4;
            float4 kv = *(const float4*)(kb + (size_t)(kt * 64 + row) * HDd + c4);
            float4 vv = *(const float4*)(vb + (size_t)(kt * 64 + row) * HDd + c4);
            uint4 kt4 = make_uint4(to_tf32(kv.x), to_tf32(kv.y), to_tf32(kv.z), to_tf32(kv.w));
            uint4 vt4 = make_uint4(to_tf32(vv.x), to_tf32(vv.y), to_tf32(vv.z), to_tf32(vv.w));
            *(uint4*)&Ks[row * KP + c4] = kt4;
            *(uint4*)&Vs[row * VP + c4] = vt4;
        }
        __syncthreads();

        float s[8][4];
        #pragma unroll
        for (int na = 0; na < 8; na++)
            #pragma unroll
            for (int i = 0; i < 4; i++) s[na][i] = 0.f;

        #pragma unroll
        for (int c = 0; c < 8; c++) {
            #pragma unroll
            for (int na = 0; na < 8; na++) {
                uint32_t b0 = Ks[(na * 8 + g) * KP + c * 8 + tig    ];
                uint32_t b1 = Ks[(na * 8 + g) * KP + c * 8 + tig + 4];
                mma_tf32(s[na], qf[c][0], qf[c][1], qf[c][2], qf[c][3], b0, b1);
            }
        }

        if (kt == nt - 1) {
            const int rlo = qr0 + g, rhi = qr0 + g + 8;
            #pragma unroll
            for (int na = 0; na < 8; na++) {
                const int c0 = kt * 64 + na * 8 + tig * 2;
                const int c1 = c0 + 1;
                if (c0 > rlo) s[na][0] = -INFINITY;
                if (c1 > rlo) s[na][1] = -INFINITY;
                if (c0 > rhi) s[na][2] = -INFINITY;
                if (c1 > rhi) s[na][3] = -INFINITY;
            }
        }

        float tm_lo = -INFINITY, tm_hi = -INFINITY;
        #pragma unroll
        for (int na = 0; na < 8; na++) {
            tm_lo = fmaxf(tm_lo, fmaxf(s[na][0], s[na][1]));
            tm_hi = fmaxf(tm_hi, fmaxf(s[na][2], s[na][3]));
        }
        tm_lo = fmaxf(tm_lo, __shfl_xor_sync(0xffffffffu, tm_lo, 1));
        tm_lo = fmaxf(tm_lo, __shfl_xor_sync(0xffffffffu, tm_lo, 2));
        tm_hi = fmaxf(tm_hi, __shfl_xor_sync(0xffffffffu, tm_hi, 1));
        tm_hi = fmaxf(tm_hi, __shfl_xor_sync(0xffffffffu, tm_hi, 2));

        const float mn_lo = fmaxf(m_lo, tm_lo);
        const float mn_hi = fmaxf(m_hi, tm_hi);
        const float sc_lo = __expf(m_lo - mn_lo);
        const float sc_hi = __expf(m_hi - mn_hi);

        float sum_lo = 0.f, sum_hi = 0.f;
        #pragma unroll
        for (int na = 0; na < 8; na++) {
            s[na][0] = __expf(s[na][0] - mn_lo);
            s[na][1] = __expf(s[na][1] - mn_lo);
            s[na][2] = __expf(s[na][2] - mn_hi);
            s[na][3] = __expf(s[na][3] - mn_hi);
            sum_lo += s[na][0] + s[na][1];
            sum_hi += s[na][2] + s[na][3];
        }
        sum_lo += __shfl_xor_sync(0xffffffffu, sum_lo, 1);
        sum_lo += __shfl_xor_sync(0xffffffffu, sum_lo, 2);
        sum_hi += __shfl_xor_sync(0xffffffffu, sum_hi, 1);
        sum_hi += __shfl_xor_sync(0xffffffffu, sum_hi, 2);

        l_lo = l_lo * sc_lo + sum_lo;  m_lo = mn_lo;
        l_hi = l_hi * sc_hi + sum_hi;  m_hi = mn_hi;

        #pragma unroll
        for (int na = 0; na < 8; na++) {
            acc[na][0] *= sc_lo; acc[na][1] *= sc_lo;
            acc[na][2] *= sc_hi; acc[na][3] *= sc_hi;
        }

        #pragma unroll
        for (int na = 0; na < 8; na++) {
            uint2 plo = make_uint2(to_tf32(s[na][0]), to_tf32(s[na][1]));
            uint2 phi = make_uint2(to_tf32(s[na][2]), to_tf32(s[na][3]));
            *(uint2*)&Pw[(g    ) * PP + na * 8 + tig * 2] = plo;
            *(uint2*)&Pw[(g + 8) * PP + na * 8 + tig * 2] = phi;
        }
        __syncwarp();

        #pragma unroll
        for (int c = 0; c < 8; c++) {
            uint32_t a0 = Pw[(g    ) * PP + c * 8 + tig    ];
            uint32_t a1 = Pw[(g + 8) * PP + c * 8 + tig    ];
            uint32_t a2 = Pw[(g    ) * PP + c * 8 + tig + 4];
            uint32_t a3 = Pw[(g + 8) * PP + c * 8 + tig + 4];
            #pragma unroll
            for (int na = 0; na < 8; na++) {
                uint32_t b0 = Vs[(c * 8 + tig    ) * VP + na * 8 + g];
                uint32_t b1 = Vs[(c * 8 + tig + 4) * VP + na * 8 + g];
                mma_tf32(acc[na], a0, a1, a2, a3, b0, b1);
            }
        }
    }

    const float inv_lo = 1.f / l_lo;
    const float inv_hi = 1.f / l_hi;
    const int b = bh / Hh, h = bh % Hh;
    float* olo = g_o + ((size_t)b * Ss + (qr0 + g    )) * Dd + h * HDd;
    float* ohi = g_o + ((size_t)b * Ss + (qr0 + g + 8)) * Dd + h * HDd;
    #pragma unroll
    for (int na = 0; na < 8; na++) {
        float2 vlo = make_float2(acc[na][0] * inv_lo, acc[na][1] * inv_lo);
        float2 vhi = make_float2(acc[na][2] * inv_hi, acc[na][3] * inv_hi);
        *(float2*)&olo[na * 8 + tig * 2] = vlo;
        *(float2*)&ohi[na * 8 + tig * 2] = vhi;
    }
}

// ---------------------------------------------------------------------------
extern "C" void kernel_launch(void* const* d_in, const int* in_sizes, int n_in,
                              void* d_out, int out_size)
{
    const float* x  = (const float*)d_in[0];
    const float* wq = (const float*)d_in[1];
    const float* bq = (const float*)d_in[2];
    const float* wk = (const float*)d_in[3];
    const float* bk = (const float*)d_in[4];
    const float* wv = (const float*)d_in[5];
    const float* bv = (const float*)d_in[6];
    const float* wo = (const float*)d_in[7];
    const float* bo = (const float*)d_in[8];
    float* out = (float*)d_out;

    cudaFuncSetAttribute(flash_attn_tc,
                         cudaFuncAttributeMaxDynamicSharedMemorySize, FA_SMEM);

    dim3 ggrid(Dd / 128, Mm / 128);       // (8, 64)
    tc_gemm<0><<<ggrid, 256>>>(x, wq, bq, nullptr);
    tc_gemm<1><<<ggrid, 256>>>(x, wk, bk, nullptr);
    tc_gemm<2><<<ggrid, 256>>>(x, wv, bv, nullptr);

    dim3 agrid(Ss / 64, Bb * Hh);         // (32, 64)
    flash_attn_tc<<<agrid, 128, FA_SMEM>>>();

    tc_gemm<3><<<ggrid, 256>>>(nullptr, wo, bo, out);
}

// round 7
// speedup vs baseline: 3.7734x; 1.1348x over previous
#include <cuda_runtime.h>
#include <math.h>
#include <stdint.h>

// Problem constants
#define Bb  4
#define Ss  2048
#define Dd  1024
#define Hh  16
#define HDd 64
#define Mm  (Bb*Ss)          // 8192

// Scratch (no allocation allowed -> __device__ globals)
__device__ __align__(16) float g_q[Bb*Hh*Ss*HDd];   // [B,H,S,HD]
__device__ __align__(16) float g_k[Bb*Hh*Ss*HDd];
__device__ __align__(16) float g_v[Bb*Hh*Ss*HDd];
__device__ __align__(16) float g_o[Bb*Ss*Dd];       // [B,S,D] (merged heads)

__device__ __forceinline__ uint32_t to_tf32(float f) {
    uint32_t u;
    asm("cvt.rna.tf32.f32 %0, %1;" : "=r"(u) : "f"(f));
    return u;
}

__device__ __forceinline__ void mma_tf32(float c[4],
                                         uint32_t a0, uint32_t a1, uint32_t a2, uint32_t a3,
                                         uint32_t b0, uint32_t b1) {
    asm volatile(
        "mma.sync.aligned.m16n8k8.row.col.f32.tf32.tf32.f32 "
        "{%0,%1,%2,%3}, {%4,%5,%6,%7}, {%8,%9}, {%0,%1,%2,%3};"
        : "+f"(c[0]), "+f"(c[1]), "+f"(c[2]), "+f"(c[3])
        : "r"(a0), "r"(a1), "r"(a2), "r"(a3), "r"(b0), "r"(b1));
}

__device__ __forceinline__ void cp16(float* dst_smem, const float* src) {
    uint32_t d = (uint32_t)__cvta_generic_to_shared(dst_smem);
    asm volatile("cp.async.cg.shared.global [%0], [%1], 16;\n" :: "r"(d), "l"(src));
}
#define CP_COMMIT() asm volatile("cp.async.commit_group;\n" ::: "memory")
#define CP_WAIT1()  asm volatile("cp.async.wait_group 1;\n" ::: "memory")

// ---------------------------------------------------------------------------
// tf32 tensor-core GEMM, 3-stage cp.async pipeline.
// out = A[M,1024] @ W[1024,1024] + bias
// MODE 0/1/2: A = x, out = g_q/g_k/g_v head-split [B,H,S,HD]
// MODE 3:     A = g_o, out = d_out row-major [M,N]
// Block tile 128x128, K-tile 16, 256 threads = 8 warps (warp tile 32x64).
// smem: raw fp32, A row-major [128][AP=20], B [16][BP=136] (pitches chosen
// conflict-free for the mma fragment gathers). cvt.rna at fragment load.
// Per iter: wait_group(1) -> barrier -> issue tile kt+2 -> compute tile kt.
// ---------------------------------------------------------------------------
#define AP 20
#define BP 136
#define ASZ (128*AP)                 // floats per A stage (2560)
#define BSZ (16*BP)                  // floats per B stage (2176)
#define GEMM_SMEM (3*(ASZ+BSZ)*4)    // 56832 bytes

template<int MODE>
__global__ __launch_bounds__(256, 2)
void tc_gemm(const float* __restrict__ A_param,
             const float* __restrict__ W,
             const float* __restrict__ bias,
             float* __restrict__ out_param)
{
    const int K = Dd, N = Dd;
    extern __shared__ float dsm[];
    float* Abuf = dsm;               // 3 stages of [128][AP]
    float* Bbuf = dsm + 3 * ASZ;     // 3 stages of [16][BP]

    const float* A = (MODE == 3) ? g_o : A_param;
    float* outp;
    if      (MODE == 0) outp = g_q;
    else if (MODE == 1) outp = g_k;
    else if (MODE == 2) outp = g_v;
    else                outp = out_param;

    const int t    = threadIdx.x;
    const int lane = t & 31;
    const int wid  = t >> 5;
    const int wm   = (wid & 3) * 32;
    const int wn   = (wid >> 2) * 64;
    const int g    = lane >> 2;
    const int tig  = lane & 3;

    const int bm = blockIdx.y * 128;
    const int bn = blockIdx.x * 128;

    // A loader: chunks (ar, kc) and (ar+64, kc): 2 x 16B per thread
    const int ar = t >> 2;            // 0..63
    const int akc = (t & 3) * 4;      // 0,4,8,12
    // B loader: chunks (brr, bcc) and (brr+8, bcc)
    const int brr = t >> 5;           // 0..7
    const int bcc = (t & 31) * 4;     // 0..124

    const float* Arow0 = A + (size_t)(bm + ar) * K + akc;
    const float* Arow1 = A + (size_t)(bm + ar + 64) * K + akc;
    const float* Wrow0 = W + (size_t)brr * N + bn + bcc;
    const float* Wrow1 = W + (size_t)(brr + 8) * N + bn + bcc;

    const int NT = K / 16;            // 64

    // issue k-tile kt into stage stg (guarded), always commit
    auto issue = [&](int kt, int stg) {
        if (kt < NT) {
            const int k0 = kt * 16;
            float* Asg = Abuf + stg * ASZ;
            float* Bsg = Bbuf + stg * BSZ;
            cp16(Asg + ar * AP + akc,        Arow0 + k0);
            cp16(Asg + (ar + 64) * AP + akc, Arow1 + k0);
            cp16(Bsg + brr * BP + bcc,       Wrow0 + (size_t)k0 * N);
            cp16(Bsg + (brr + 8) * BP + bcc, Wrow1 + (size_t)k0 * N);
        }
        CP_COMMIT();
    };

    float acc[2][8][4];
    #pragma unroll
    for (int ma = 0; ma < 2; ma++)
        #pragma unroll
        for (int na = 0; na < 8; na++)
            #pragma unroll
            for (int i = 0; i < 4; i++) acc[ma][na][i] = 0.f;

    // prologue: tiles 0,1
    issue(0, 0);
    issue(1, 1);

    for (int kt = 0; kt < NT; kt++) {
        const int cur = kt % 3;
        CP_WAIT1();                   // tile kt landed (<=1 group in flight)
        __syncthreads();              // all threads' copies visible; stage (kt-1)%3 free
        issue(kt + 2, (kt + 2) % 3);

        const float* Asg = Abuf + cur * ASZ;
        const float* Bsg = Bbuf + cur * BSZ;

        #pragma unroll
        for (int ks = 0; ks < 16; ks += 8) {
            uint32_t a[2][4];
            #pragma unroll
            for (int ma = 0; ma < 2; ma++) {
                const int m0 = wm + ma * 16 + g;
                a[ma][0] = to_tf32(Asg[(m0    ) * AP + ks + tig    ]);
                a[ma][1] = to_tf32(Asg[(m0 + 8) * AP + ks + tig    ]);
                a[ma][2] = to_tf32(Asg[(m0    ) * AP + ks + tig + 4]);
                a[ma][3] = to_tf32(Asg[(m0 + 8) * AP + ks + tig + 4]);
            }
            #pragma unroll
            for (int na = 0; na < 8; na++) {
                const int n0 = wn + na * 8 + g;
                uint32_t b0 = to_tf32(Bsg[(ks + tig    ) * BP + n0]);
                uint32_t b1 = to_tf32(Bsg[(ks + tig + 4) * BP + n0]);
                #pragma unroll
                for (int ma = 0; ma < 2; ma++)
                    mma_tf32(acc[ma][na], a[ma][0], a[ma][1], a[ma][2], a[ma][3], b0, b1);
            }
        }
    }

    // ---- epilogue: bias + store ----
    #pragma unroll
    for (int ma = 0; ma < 2; ma++) {
        #pragma unroll
        for (int na = 0; na < 8; na++) {
            const int row0 = bm + wm + ma * 16 + g;
            const int col  = bn + wn + na * 8 + tig * 2;
            const float bia0 = bias[col], bia1 = bias[col + 1];
            #pragma unroll
            for (int half = 0; half < 2; half++) {
                const int mrow = row0 + half * 8;
                float2 v;
                v.x = acc[ma][na][half * 2 + 0] + bia0;
                v.y = acc[ma][na][half * 2 + 1] + bia1;
                if (MODE <= 2) {
                    const int b = mrow / Ss, s = mrow % Ss;
                    const int h = col / HDd, d = col % HDd;
                    *(float2*)&outp[(((size_t)b * Hh + h) * Ss + s) * HDd + d] = v;
                } else {
                    *(float2*)&outp[(size_t)mrow * Dd + col] = v;
                }
            }
        }
    }
}

// ---------------------------------------------------------------------------
// Tensor-core flash attention (causal), tf32 mma, FA2-style (unchanged).
// ---------------------------------------------------------------------------
#define KP 68
#define VP 72
#define PP 68
#define FA_SMEM ((64*KP + 64*VP + 4*16*PP) * 4)   // 53248 bytes

__global__ __launch_bounds__(128)
void flash_attn_tc()
{
    extern __shared__ uint32_t dsmu[];
    uint32_t* Ks = dsmu;                     // [64][KP]
    uint32_t* Vs = dsmu + 64 * KP;           // [64][VP]
    uint32_t* Ps = dsmu + 64 * KP + 64 * VP; // [4][16][PP]

    const int tid  = threadIdx.x;
    const int lane = tid & 31;
    const int wid  = tid >> 5;
    const int g    = lane >> 2;
    const int tig  = lane & 3;
    const int q0   = blockIdx.x * 64;
    const int bh   = blockIdx.y;
    const int qr0  = q0 + wid * 16;

    const float* qb = g_q + (size_t)bh * Ss * HDd;
    const float* kb = g_k + (size_t)bh * Ss * HDd;
    const float* vb = g_v + (size_t)bh * Ss * HDd;

    uint32_t qf[8][4];
    #pragma unroll
    for (int c = 0; c < 8; c++) {
        qf[c][0] = to_tf32(qb[(size_t)(qr0 + g    ) * HDd + c * 8 + tig    ] * 0.125f);
        qf[c][1] = to_tf32(qb[(size_t)(qr0 + g + 8) * HDd + c * 8 + tig    ] * 0.125f);
        qf[c][2] = to_tf32(qb[(size_t)(qr0 + g    ) * HDd + c * 8 + tig + 4] * 0.125f);
        qf[c][3] = to_tf32(qb[(size_t)(qr0 + g + 8) * HDd + c * 8 + tig + 4] * 0.125f);
    }

    float acc[8][4];
    #pragma unroll
    for (int na = 0; na < 8; na++)
        #pragma unroll
        for (int i = 0; i < 4; i++) acc[na][i] = 0.f;

    float m_lo = -INFINITY, m_hi = -INFINITY;
    float l_lo = 0.f, l_hi = 0.f;

    uint32_t* Pw = Ps + wid * 16 * PP;
    const int nt = q0 / 64 + 1;

    for (int kt = 0; kt < nt; kt++) {
        __syncthreads();
        #pragma unroll
        for (int i = 0; i < 8; i++) {
            const int idx = tid + i * 128;
            const int row = idx >> 4;
            const int c4  = (idx & 15) * 4;
            float4 kv = *(const float4*)(kb + (size_t)(kt * 64 + row) * HDd + c4);
            float4 vv = *(const float4*)(vb + (size_t)(kt * 64 + row) * HDd + c4);
            uint4 kt4 = make_uint4(to_tf32(kv.x), to_tf32(kv.y), to_tf32(kv.z), to_tf32(kv.w));
            uint4 vt4 = make_uint4(to_tf32(vv.x), to_tf32(vv.y), to_tf32(vv.z), to_tf32(vv.w));
            *(uint4*)&Ks[row * KP + c4] = kt4;
            *(uint4*)&Vs[row * VP + c4] = vt4;
        }
        __syncthreads();

        float s[8][4];
        #pragma unroll
        for (int na = 0; na < 8; na++)
            #pragma unroll
            for (int i = 0; i < 4; i++) s[na][i] = 0.f;

        #pragma unroll
        for (int c = 0; c < 8; c++) {
            #pragma unroll
            for (int na = 0; na < 8; na++) {
                uint32_t b0 = Ks[(na * 8 + g) * KP + c * 8 + tig    ];
                uint32_t b1 = Ks[(na * 8 + g) * KP + c * 8 + tig + 4];
                mma_tf32(s[na], qf[c][0], qf[c][1], qf[c][2], qf[c][3], b0, b1);
            }
        }

        if (kt == nt - 1) {
            const int rlo = qr0 + g, rhi = qr0 + g + 8;
            #pragma unroll
            for (int na = 0; na < 8; na++) {
                const int c0 = kt * 64 + na * 8 + tig * 2;
                const int c1 = c0 + 1;
                if (c0 > rlo) s[na][0] = -INFINITY;
                if (c1 > rlo) s[na][1] = -INFINITY;
                if (c0 > rhi) s[na][2] = -INFINITY;
                if (c1 > rhi) s[na][3] = -INFINITY;
            }
        }

        float tm_lo = -INFINITY, tm_hi = -INFINITY;
        #pragma unroll
        for (int na = 0; na < 8; na++) {
            tm_lo = fmaxf(tm_lo, fmaxf(s[na][0], s[na][1]));
            tm_hi = fmaxf(tm_hi, fmaxf(s[na][2], s[na][3]));
        }
        tm_lo = fmaxf(tm_lo, __shfl_xor_sync(0xffffffffu, tm_lo, 1));
        tm_lo = fmaxf(tm_lo, __shfl_xor_sync(0xffffffffu, tm_lo, 2));
        tm_hi = fmaxf(tm_hi, __shfl_xor_sync(0xffffffffu, tm_hi, 1));
        tm_hi = fmaxf(tm_hi, __shfl_xor_sync(0xffffffffu, tm_hi, 2));

        const float mn_lo = fmaxf(m_lo, tm_lo);
        const float mn_hi = fmaxf(m_hi, tm_hi);
        const float sc_lo = __expf(m_lo - mn_lo);
        const float sc_hi = __expf(m_hi - mn_hi);

        float sum_lo = 0.f, sum_hi = 0.f;
        #pragma unroll
        for (int na = 0; na < 8; na++) {
            s[na][0] = __expf(s[na][0] - mn_lo);
            s[na][1] = __expf(s[na][1] - mn_lo);
            s[na][2] = __expf(s[na][2] - mn_hi);
            s[na][3] = __expf(s[na][3] - mn_hi);
            sum_lo += s[na][0] + s[na][1];
            sum_hi += s[na][2] + s[na][3];
        }
        sum_lo += __shfl_xor_sync(0xffffffffu, sum_lo, 1);
        sum_lo += __shfl_xor_sync(0xffffffffu, sum_lo, 2);
        sum_hi += __shfl_xor_sync(0xffffffffu, sum_hi, 1);
        sum_hi += __shfl_xor_sync(0xffffffffu, sum_hi, 2);

        l_lo = l_lo * sc_lo + sum_lo;  m_lo = mn_lo;
        l_hi = l_hi * sc_hi + sum_hi;  m_hi = mn_hi;

        #pragma unroll
        for (int na = 0; na < 8; na++) {
            acc[na][0] *= sc_lo; acc[na][1] *= sc_lo;
            acc[na][2] *= sc_hi; acc[na][3] *= sc_hi;
        }

        #pragma unroll
        for (int na = 0; na < 8; na++) {
            uint2 plo = make_uint2(to_tf32(s[na][0]), to_tf32(s[na][1]));
            uint2 phi = make_uint2(to_tf32(s[na][2]), to_tf32(s[na][3]));
            *(uint2*)&Pw[(g    ) * PP + na * 8 + tig * 2] = plo;
            *(uint2*)&Pw[(g + 8) * PP + na * 8 + tig * 2] = phi;
        }
        __syncwarp();

        #pragma unroll
        for (int c = 0; c < 8; c++) {
            uint32_t a0 = Pw[(g    ) * PP + c * 8 + tig    ];
            uint32_t a1 = Pw[(g + 8) * PP + c * 8 + tig    ];
            uint32_t a2 = Pw[(g    ) * PP + c * 8 + tig + 4];
            uint32_t a3 = Pw[(g + 8) * PP + c * 8 + tig + 4];
            #pragma unroll
            for (int na = 0; na < 8; na++) {
                uint32_t b0 = Vs[(c * 8 + tig    ) * VP + na * 8 + g];
                uint32_t b1 = Vs[(c * 8 + tig + 4) * VP + na * 8 + g];
                mma_tf32(acc[na], a0, a1, a2, a3, b0, b1);
            }
        }
    }

    const float inv_lo = 1.f / l_lo;
    const float inv_hi = 1.f / l_hi;
    const int b = bh / Hh, h = bh % Hh;
    float* olo = g_o + ((size_t)b * Ss + (qr0 + g    )) * Dd + h * HDd;
    float* ohi = g_o + ((size_t)b * Ss + (qr0 + g + 8)) * Dd + h * HDd;
    #pragma unroll
    for (int na = 0; na < 8; na++) {
        float2 vlo = make_float2(acc[na][0] * inv_lo, acc[na][1] * inv_lo);
        float2 vhi = make_float2(acc[na][2] * inv_hi, acc[na][3] * inv_hi);
        *(float2*)&olo[na * 8 + tig * 2] = vlo;
        *(float2*)&ohi[na * 8 + tig * 2] = vhi;
    }
}

// ---------------------------------------------------------------------------
extern "C" void kernel_launch(void* const* d_in, const int* in_sizes, int n_in,
                              void* d_out, int out_size)
{
    const float* x  = (const float*)d_in[0];
    const float* wq = (const float*)d_in[1];
    const float* bq = (const float*)d_in[2];
    const float* wk = (const float*)d_in[3];
    const float* bk = (const float*)d_in[4];
    const float* wv = (const float*)d_in[5];
    const float* bv = (const float*)d_in[6];
    const float* wo = (const float*)d_in[7];
    const float* bo = (const float*)d_in[8];
    float* out = (float*)d_out;

    cudaFuncSetAttribute(tc_gemm<0>, cudaFuncAttributeMaxDynamicSharedMemorySize, GEMM_SMEM);
    cudaFuncSetAttribute(tc_gemm<1>, cudaFuncAttributeMaxDynamicSharedMemorySize, GEMM_SMEM);
    cudaFuncSetAttribute(tc_gemm<2>, cudaFuncAttributeMaxDynamicSharedMemorySize, GEMM_SMEM);
    cudaFuncSetAttribute(tc_gemm<3>, cudaFuncAttributeMaxDynamicSharedMemorySize, GEMM_SMEM);
    cudaFuncSetAttribute(flash_attn_tc,
                         cudaFuncAttributeMaxDynamicSharedMemorySize, FA_SMEM);

    dim3 ggrid(Dd / 128, Mm / 128);       // (8, 64)
    tc_gemm<0><<<ggrid, 256, GEMM_SMEM>>>(x, wq, bq, nullptr);
    tc_gemm<1><<<ggrid, 256, GEMM_SMEM>>>(x, wk, bk, nullptr);
    tc_gemm<2><<<ggrid, 256, GEMM_SMEM>>>(x, wv, bv, nullptr);

    dim3 agrid(Ss / 64, Bb * Hh);         // (32, 64)
    flash_attn_tc<<<agrid, 128, FA_SMEM>>>();

    tc_gemm<3><<<ggrid, 256, GEMM_SMEM>>>(nullptr, wo, bo, out);
}

// round 8
// speedup vs baseline: 4.3693x; 1.1579x over previous
#include <cuda_runtime.h>
#include <math.h>
#include <stdint.h>

// Problem constants
#define Bb  4
#define Ss  2048
#define Dd  1024
#define Hh  16
#define HDd 64
#define Mm  (Bb*Ss)          // 8192

// Scratch (no allocation allowed -> __device__ globals)
__device__ __align__(16) float g_q[Bb*Hh*Ss*HDd];   // [B,H,S,HD] (tf32-rounded)
__device__ __align__(16) float g_k[Bb*Hh*Ss*HDd];   // (tf32-rounded)
__device__ __align__(16) float g_v[Bb*Hh*Ss*HDd];   // (tf32-rounded)
__device__ __align__(16) float g_o[Bb*Ss*Dd];       // [B,S,D] (tf32-rounded)
__device__ __align__(16) float g_xt[Mm*Dd];         // x rounded to tf32
__device__ __align__(16) float g_wt[4][Dd*Dd];      // wq,wk,wv,wo rounded

__device__ __forceinline__ uint32_t to_tf32(float f) {
    uint32_t u;
    asm("cvt.rna.tf32.f32 %0, %1;" : "=r"(u) : "f"(f));
    return u;
}

__device__ __forceinline__ void mma_tf32(float c[4],
                                         uint32_t a0, uint32_t a1, uint32_t a2, uint32_t a3,
                                         uint32_t b0, uint32_t b1) {
    asm volatile(
        "mma.sync.aligned.m16n8k8.row.col.f32.tf32.tf32.f32 "
        "{%0,%1,%2,%3}, {%4,%5,%6,%7}, {%8,%9}, {%0,%1,%2,%3};"
        : "+f"(c[0]), "+f"(c[1]), "+f"(c[2]), "+f"(c[3])
        : "r"(a0), "r"(a1), "r"(a2), "r"(a3), "r"(b0), "r"(b1));
}

__device__ __forceinline__ void cp16(void* dst_smem, const void* src) {
    uint32_t d = (uint32_t)__cvta_generic_to_shared(dst_smem);
    asm volatile("cp.async.cg.shared.global [%0], [%1], 16;\n" :: "r"(d), "l"(src));
}
#define CP_COMMIT() asm volatile("cp.async.commit_group;\n" ::: "memory")
#define CP_WAIT1()  asm volatile("cp.async.wait_group 1;\n" ::: "memory")
#define CP_WAIT0()  asm volatile("cp.async.wait_group 0;\n" ::: "memory")

// ---------------------------------------------------------------------------
// Pre-pass: round x and the 4 weight matrices to tf32 (cvt.rna), once.
// chunk = 4 floats. x: 2M chunks (blocks 0..8191); w[i]: 256K chunks each.
// ---------------------------------------------------------------------------
__global__ __launch_bounds__(256)
void round_all(const float* __restrict__ x,
               const float* __restrict__ wq, const float* __restrict__ wk,
               const float* __restrict__ wv, const float* __restrict__ wo)
{
    const int bid = blockIdx.x;
    const float* src; float* dst; size_t base;
    if (bid < 8192) { src = x; dst = g_xt; base = (size_t)bid * 1024; }
    else {
        const int w = (bid - 8192) >> 10;           // 0..3
        const int wb = (bid - 8192) & 1023;
        src = (w == 0) ? wq : (w == 1) ? wk : (w == 2) ? wv : wo;
        dst = g_wt[w]; base = (size_t)wb * 1024;
    }
    const size_t i = base + threadIdx.x * 4;
    float4 v = *(const float4*)(src + i);
    uint4 r = make_uint4(to_tf32(v.x), to_tf32(v.y), to_tf32(v.z), to_tf32(v.w));
    *(uint4*)(dst + i) = r;
}

// ---------------------------------------------------------------------------
// tf32 tensor-core GEMM, 3-stage cp.async pipeline, NO cvt in mainloop
// (inputs pre-rounded; raw bits fed to mma).
// QKV=true:  grid (24,64). blockIdx.x>>3 selects Q/K/V; A=g_xt, W=g_wt[sel],
//            out = g_q/g_k/g_v head-split [B,H,S,HD], values tf32-rounded.
// QKV=false: grid (8,64). A=g_o (pre-rounded by flash), W=g_wt[3],
//            out = d_out row-major full precision.
// ---------------------------------------------------------------------------
#define AP 20
#define BP 136
#define ASZ (128*AP)
#define BSZ (16*BP)
#define GEMM_SMEM (3*(ASZ+BSZ)*4)    // 56832 bytes

template<bool QKV>
__global__ __launch_bounds__(256, 2)
void tc_gemm(const float* __restrict__ bq, const float* __restrict__ bk,
             const float* __restrict__ bv, const float* __restrict__ bo,
             float* __restrict__ out_param)
{
    const int K = Dd, N = Dd;
    extern __shared__ float dsm[];
    float* Abuf = dsm;
    float* Bbuf = dsm + 3 * ASZ;

    int sel; const float* A; const float* W; const float* bias; float* outp;
    int bnx;
    if (QKV) {
        sel = blockIdx.x >> 3;  bnx = blockIdx.x & 7;
        A = g_xt;  W = g_wt[sel];
        bias = (sel == 0) ? bq : (sel == 1) ? bk : bv;
        outp = (sel == 0) ? g_q : (sel == 1) ? g_k : g_v;
    } else {
        sel = 3; bnx = blockIdx.x;
        A = g_o;  W = g_wt[3];  bias = bo;  outp = out_param;
    }

    const int t    = threadIdx.x;
    const int lane = t & 31;
    const int wid  = t >> 5;
    const int wm   = (wid & 3) * 32;
    const int wn   = (wid >> 2) * 64;
    const int g    = lane >> 2;
    const int tig  = lane & 3;

    const int bm = blockIdx.y * 128;
    const int bn = bnx * 128;

    const int ar = t >> 2;
    const int akc = (t & 3) * 4;
    const int brr = t >> 5;
    const int bcc = (t & 31) * 4;

    const float* Arow0 = A + (size_t)(bm + ar) * K + akc;
    const float* Arow1 = A + (size_t)(bm + ar + 64) * K + akc;
    const float* Wrow0 = W + (size_t)brr * N + bn + bcc;
    const float* Wrow1 = W + (size_t)(brr + 8) * N + bn + bcc;

    const int NT = K / 16;

    auto issue = [&](int kt, int stg) {
        if (kt < NT) {
            const int k0 = kt * 16;
            float* Asg = Abuf + stg * ASZ;
            float* Bsg = Bbuf + stg * BSZ;
            cp16(Asg + ar * AP + akc,        Arow0 + k0);
            cp16(Asg + (ar + 64) * AP + akc, Arow1 + k0);
            cp16(Bsg + brr * BP + bcc,       Wrow0 + (size_t)k0 * N);
            cp16(Bsg + (brr + 8) * BP + bcc, Wrow1 + (size_t)k0 * N);
        }
        CP_COMMIT();
    };

    float acc[2][8][4];
    #pragma unroll
    for (int ma = 0; ma < 2; ma++)
        #pragma unroll
        for (int na = 0; na < 8; na++)
            #pragma unroll
            for (int i = 0; i < 4; i++) acc[ma][na][i] = 0.f;

    issue(0, 0);
    issue(1, 1);

    for (int kt = 0; kt < NT; kt++) {
        const int cur = kt % 3;
        CP_WAIT1();
        __syncthreads();
        issue(kt + 2, (kt + 2) % 3);

        const uint32_t* Asg = (const uint32_t*)(Abuf + cur * ASZ);
        const uint32_t* Bsg = (const uint32_t*)(Bbuf + cur * BSZ);

        #pragma unroll
        for (int ks = 0; ks < 16; ks += 8) {
            uint32_t a[2][4];
            #pragma unroll
            for (int ma = 0; ma < 2; ma++) {
                const int m0 = wm + ma * 16 + g;
                a[ma][0] = Asg[(m0    ) * AP + ks + tig    ];
                a[ma][1] = Asg[(m0 + 8) * AP + ks + tig    ];
                a[ma][2] = Asg[(m0    ) * AP + ks + tig + 4];
                a[ma][3] = Asg[(m0 + 8) * AP + ks + tig + 4];
            }
            #pragma unroll
            for (int na = 0; na < 8; na++) {
                const int n0 = wn + na * 8 + g;
                uint32_t b0 = Bsg[(ks + tig    ) * BP + n0];
                uint32_t b1 = Bsg[(ks + tig + 4) * BP + n0];
                #pragma unroll
                for (int ma = 0; ma < 2; ma++)
                    mma_tf32(acc[ma][na], a[ma][0], a[ma][1], a[ma][2], a[ma][3], b0, b1);
            }
        }
    }

    // ---- epilogue: bias + store (QKV: tf32-rounded head-split) ----
    #pragma unroll
    for (int ma = 0; ma < 2; ma++) {
        #pragma unroll
        for (int na = 0; na < 8; na++) {
            const int row0 = bm + wm + ma * 16 + g;
            const int col  = bn + wn + na * 8 + tig * 2;
            const float bia0 = bias[col], bia1 = bias[col + 1];
            #pragma unroll
            for (int half = 0; half < 2; half++) {
                const int mrow = row0 + half * 8;
                const float v0 = acc[ma][na][half * 2 + 0] + bia0;
                const float v1 = acc[ma][na][half * 2 + 1] + bia1;
                if (QKV) {
                    const int b = mrow / Ss, s = mrow % Ss;
                    const int h = col / HDd, d = col % HDd;
                    uint2 r = make_uint2(to_tf32(v0), to_tf32(v1));
                    *(uint2*)&outp[(((size_t)b * Hh + h) * Ss + s) * HDd + d] = r;
                } else {
                    *(float2*)&outp[(size_t)mrow * Dd + col] = make_float2(v0, v1);
                }
            }
        }
    }
}

// ---------------------------------------------------------------------------
// Tensor-core flash attention (causal), tf32 mma, FA2-style.
// Now: K/V via cp.async (no conversion needed — inputs pre-rounded),
// double-buffered to overlap tile kt+1 load with tile kt compute.
// ---------------------------------------------------------------------------
#define KP 68
#define VP 72
#define PP 68
#define KSZ (64*KP)
#define VSZ (64*VP)
#define FA_SMEM ((2*KSZ + 2*VSZ + 4*16*PP) * 4)   // 89088 bytes

__global__ __launch_bounds__(128)
void flash_attn_tc()
{
    extern __shared__ uint32_t dsmu[];
    uint32_t* Ks = dsmu;                       // [2][64][KP]
    uint32_t* Vs = dsmu + 2 * KSZ;             // [2][64][VP]
    uint32_t* Ps = dsmu + 2 * KSZ + 2 * VSZ;   // [4][16][PP]

    const int tid  = threadIdx.x;
    const int lane = tid & 31;
    const int wid  = tid >> 5;
    const int g    = lane >> 2;
    const int tig  = lane & 3;
    const int q0   = blockIdx.x * 64;
    const int bh   = blockIdx.y;
    const int qr0  = q0 + wid * 16;

    const float* qb = g_q + (size_t)bh * Ss * HDd;
    const float* kb = g_k + (size_t)bh * Ss * HDd;
    const float* vb = g_v + (size_t)bh * Ss * HDd;

    // q pre-rounded; *0.125 is exact (power of 2) -> bits valid tf32
    uint32_t qf[8][4];
    #pragma unroll
    for (int c = 0; c < 8; c++) {
        qf[c][0] = __float_as_uint(qb[(size_t)(qr0 + g    ) * HDd + c * 8 + tig    ] * 0.125f);
        qf[c][1] = __float_as_uint(qb[(size_t)(qr0 + g + 8) * HDd + c * 8 + tig    ] * 0.125f);
        qf[c][2] = __float_as_uint(qb[(size_t)(qr0 + g    ) * HDd + c * 8 + tig + 4] * 0.125f);
        qf[c][3] = __float_as_uint(qb[(size_t)(qr0 + g + 8) * HDd + c * 8 + tig + 4] * 0.125f);
    }

    float acc[8][4];
    #pragma unroll
    for (int na = 0; na < 8; na++)
        #pragma unroll
        for (int i = 0; i < 4; i++) acc[na][i] = 0.f;

    float m_lo = -INFINITY, m_hi = -INFINITY;
    float l_lo = 0.f, l_hi = 0.f;

    uint32_t* Pw = Ps + wid * 16 * PP;
    const int nt = q0 / 64 + 1;

    auto issue_tile = [&](int kt, int buf) {
        const float* ksrc = kb + (size_t)kt * 64 * HDd;
        const float* vsrc = vb + (size_t)kt * 64 * HDd;
        uint32_t* Kd = Ks + buf * KSZ;
        uint32_t* Vd = Vs + buf * VSZ;
        #pragma unroll
        for (int i = 0; i < 8; i++) {
            const int idx = tid + i * 128;
            const int row = idx >> 4;
            const int c4  = (idx & 15) * 4;
            cp16(&Kd[row * KP + c4], ksrc + row * HDd + c4);
            cp16(&Vd[row * VP + c4], vsrc + row * HDd + c4);
        }
        CP_COMMIT();
    };

    issue_tile(0, 0);

    for (int kt = 0; kt < nt; kt++) {
        const int cur = kt & 1;
        CP_WAIT0();
        __syncthreads();
        if (kt + 1 < nt) issue_tile(kt + 1, cur ^ 1);

        const uint32_t* Kc = Ks + cur * KSZ;
        const uint32_t* Vc = Vs + cur * VSZ;

        float s[8][4];
        #pragma unroll
        for (int na = 0; na < 8; na++)
            #pragma unroll
            for (int i = 0; i < 4; i++) s[na][i] = 0.f;

        #pragma unroll
        for (int c = 0; c < 8; c++) {
            #pragma unroll
            for (int na = 0; na < 8; na++) {
                uint32_t b0 = Kc[(na * 8 + g) * KP + c * 8 + tig    ];
                uint32_t b1 = Kc[(na * 8 + g) * KP + c * 8 + tig + 4];
                mma_tf32(s[na], qf[c][0], qf[c][1], qf[c][2], qf[c][3], b0, b1);
            }
        }

        if (kt == nt - 1) {
            const int rlo = qr0 + g, rhi = qr0 + g + 8;
            #pragma unroll
            for (int na = 0; na < 8; na++) {
                const int c0 = kt * 64 + na * 8 + tig * 2;
                const int c1 = c0 + 1;
                if (c0 > rlo) s[na][0] = -INFINITY;
                if (c1 > rlo) s[na][1] = -INFINITY;
                if (c0 > rhi) s[na][2] = -INFINITY;
                if (c1 > rhi) s[na][3] = -INFINITY;
            }
        }

        float tm_lo = -INFINITY, tm_hi = -INFINITY;
        #pragma unroll
        for (int na = 0; na < 8; na++) {
            tm_lo = fmaxf(tm_lo, fmaxf(s[na][0], s[na][1]));
            tm_hi = fmaxf(tm_hi, fmaxf(s[na][2], s[na][3]));
        }
        tm_lo = fmaxf(tm_lo, __shfl_xor_sync(0xffffffffu, tm_lo, 1));
        tm_lo = fmaxf(tm_lo, __shfl_xor_sync(0xffffffffu, tm_lo, 2));
        tm_hi = fmaxf(tm_hi, __shfl_xor_sync(0xffffffffu, tm_hi, 1));
        tm_hi = fmaxf(tm_hi, __shfl_xor_sync(0xffffffffu, tm_hi, 2));

        const float mn_lo = fmaxf(m_lo, tm_lo);
        const float mn_hi = fmaxf(m_hi, tm_hi);
        const float sc_lo = __expf(m_lo - mn_lo);
        const float sc_hi = __expf(m_hi - mn_hi);

        float sum_lo = 0.f, sum_hi = 0.f;
        #pragma unroll
        for (int na = 0; na < 8; na++) {
            s[na][0] = __expf(s[na][0] - mn_lo);
            s[na][1] = __expf(s[na][1] - mn_lo);
            s[na][2] = __expf(s[na][2] - mn_hi);
            s[na][3] = __expf(s[na][3] - mn_hi);
            sum_lo += s[na][0] + s[na][1];
            sum_hi += s[na][2] + s[na][3];
        }
        sum_lo += __shfl_xor_sync(0xffffffffu, sum_lo, 1);
        sum_lo += __shfl_xor_sync(0xffffffffu, sum_lo, 2);
        sum_hi += __shfl_xor_sync(0xffffffffu, sum_hi, 1);
        sum_hi += __shfl_xor_sync(0xffffffffu, sum_hi, 2);

        l_lo = l_lo * sc_lo + sum_lo;  m_lo = mn_lo;
        l_hi = l_hi * sc_hi + sum_hi;  m_hi = mn_hi;

        #pragma unroll
        for (int na = 0; na < 8; na++) {
            acc[na][0] *= sc_lo; acc[na][1] *= sc_lo;
            acc[na][2] *= sc_hi; acc[na][3] *= sc_hi;
        }

        #pragma unroll
        for (int na = 0; na < 8; na++) {
            uint2 plo = make_uint2(to_tf32(s[na][0]), to_tf32(s[na][1]));
            uint2 phi = make_uint2(to_tf32(s[na][2]), to_tf32(s[na][3]));
            *(uint2*)&Pw[(g    ) * PP + na * 8 + tig * 2] = plo;
            *(uint2*)&Pw[(g + 8) * PP + na * 8 + tig * 2] = phi;
        }
        __syncwarp();

        #pragma unroll
        for (int c = 0; c < 8; c++) {
            uint32_t a0 = Pw[(g    ) * PP + c * 8 + tig    ];
            uint32_t a1 = Pw[(g + 8) * PP + c * 8 + tig    ];
            uint32_t a2 = Pw[(g    ) * PP + c * 8 + tig + 4];
            uint32_t a3 = Pw[(g + 8) * PP + c * 8 + tig + 4];
            #pragma unroll
            for (int na = 0; na < 8; na++) {
                uint32_t b0 = Vc[(c * 8 + tig    ) * VP + na * 8 + g];
                uint32_t b1 = Vc[(c * 8 + tig + 4) * VP + na * 8 + g];
                mma_tf32(acc[na], a0, a1, a2, a3, b0, b1);
            }
        }
    }

    // epilogue: normalize, round to tf32 (feeds O-GEMM A operand), write
    const float inv_lo = 1.f / l_lo;
    const float inv_hi = 1.f / l_hi;
    const int b = bh / Hh, h = bh % Hh;
    float* olo = g_o + ((size_t)b * Ss + (qr0 + g    )) * Dd + h * HDd;
    float* ohi = g_o + ((size_t)b * Ss + (qr0 + g + 8)) * Dd + h * HDd;
    #pragma unroll
    for (int na = 0; na < 8; na++) {
        uint2 vlo = make_uint2(to_tf32(acc[na][0] * inv_lo), to_tf32(acc[na][1] * inv_lo));
        uint2 vhi = make_uint2(to_tf32(acc[na][2] * inv_hi), to_tf32(acc[na][3] * inv_hi));
        *(uint2*)&olo[na * 8 + tig * 2] = vlo;
        *(uint2*)&ohi[na * 8 + tig * 2] = vhi;
    }
}

// ---------------------------------------------------------------------------
extern "C" void kernel_launch(void* const* d_in, const int* in_sizes, int n_in,
                              void* d_out, int out_size)
{
    const float* x  = (const float*)d_in[0];
    const float* wq = (const float*)d_in[1];
    const float* bq = (const float*)d_in[2];
    const float* wk = (const float*)d_in[3];
    const float* bk = (const float*)d_in[4];
    const float* wv = (const float*)d_in[5];
    const float* bv = (const float*)d_in[6];
    const float* wo = (const float*)d_in[7];
    const float* bo = (const float*)d_in[8];
    float* out = (float*)d_out;

    cudaFuncSetAttribute(tc_gemm<true>,  cudaFuncAttributeMaxDynamicSharedMemorySize, GEMM_SMEM);
    cudaFuncSetAttribute(tc_gemm<false>, cudaFuncAttributeMaxDynamicSharedMemorySize, GEMM_SMEM);
    cudaFuncSetAttribute(flash_attn_tc,  cudaFuncAttributeMaxDynamicSharedMemorySize, FA_SMEM);

    // pre-round x + weights to tf32
    round_all<<<8192 + 4 * 1024, 256>>>(x, wq, wk, wv, wo);

    // fused QKV projection
    dim3 qgrid(24, Mm / 128);             // (24, 64)
    tc_gemm<true><<<qgrid, 256, GEMM_SMEM>>>(bq, bk, bv, nullptr, nullptr);

    // attention
    dim3 agrid(Ss / 64, Bb * Hh);         // (32, 64)
    flash_attn_tc<<<agrid, 128, FA_SMEM>>>();

    // output projection
    dim3 ogrid(8, Mm / 128);              // (8, 64)
    tc_gemm<false><<<ogrid, 256, GEMM_SMEM>>>(nullptr, nullptr, nullptr, bo, out);
}